// round 15
// baseline (speedup 1.0000x reference)
#include <cuda_runtime.h>
#include <math.h>
#include <stdint.h>

#define BB 128
#define LL 512
#define DD 768
#define JJ 32
#define SS 33      // J+1 segments
#define DM 200
#define DF 200
#define ROWS (BB*SS)   // 4224
#define CHUNK 8

// ---------------- scratch (no allocations allowed) ----------------
__device__ float g_pooled[ROWS * DD];   // [B*S, 768]
__device__ float g_x0[ROWS * DM];       // fc1 output
__device__ float g_qkv[ROWS * 3 * DM];  // qkv
__device__ float g_att[ROWS * DM];      // attention output (pre out-proj)
__device__ float g_y[ROWS * DM];        // pre-LN buffer
__device__ float g_x1[ROWS * DM];       // post-LN1
__device__ float g_f[ROWS * DM];        // ffn hidden
__device__ float g_x2[ROWS * DM];       // post-LN2

// ---------------- cp.async helpers ----------------
__device__ __forceinline__ void cp_async16(float* smem_dst, const float* gsrc, int src_bytes) {
    uint32_t s = (uint32_t)__cvta_generic_to_shared(smem_dst);
    asm volatile("cp.async.cg.shared.global [%0], [%1], 16, %2;"
                 :: "r"(s), "l"(gsrc), "r"(src_bytes));
}
__device__ __forceinline__ void cp_commit() {
    asm volatile("cp.async.commit_group;");
}
template <int N>
__device__ __forceinline__ void cp_wait() {
    asm volatile("cp.async.wait_group %0;" :: "n"(N));
}

// =====================================================================
// Kernel 1: fused fc5 scores + per-segment softmax + pooling.
// cp.async double-buffered, CHUNK=8, ~52 KB smem.
// =====================================================================
__global__ __launch_bounds__(256) void pool_kernel(
        const float* __restrict__ hidden,
        const int* __restrict__ cidx,
        const float* __restrict__ fc5_w,
        const float* __restrict__ fc5_b,
        float* __restrict__ pooled) {
    extern __shared__ float sm[];
    float* s_w      = sm;                        // [768]
    float* s_rows   = sm + DD;                   // [2][CHUNK][768]
    float* s_scores = s_rows + 2 * CHUNK * DD;   // [CHUNK]

    int blk = blockIdx.x;
    int b = blk / SS, s = blk % SS;
    int t0 = (s == 0)  ? 0  : cidx[b * JJ + s - 1];
    int t1 = (s == JJ) ? LL : cidx[b * JJ + s];

    int tid = threadIdx.x;
    int lane = tid & 31, wid = tid >> 5;

    const float* hb = hidden + (long)b * LL * DD;

    auto stage = [&](int c, int buf) {
        int nt = min(CHUNK, t1 - c);
        float* dst = s_rows + buf * (CHUNK * DD);
        int total = nt * (DD / 4);
        for (int idx = tid; idx < total; idx += 256) {
            int tok = idx / (DD / 4);
            int q   = idx % (DD / 4);
            cp_async16(dst + tok * DD + q * 4,
                       hb + (long)(c + tok) * DD + q * 4, 16);
        }
    };

    for (int i = tid; i < DD / 4; i += 256)
        ((float4*)s_w)[i] = ((const float4*)fc5_w)[i];
    stage(t0, 0);
    cp_commit();

    const int d0 = tid, d1 = tid + 256, d2 = tid + 512;
    float acc0 = 0.f, acc1 = 0.f, acc2 = 0.f;
    float m = -INFINITY, l = 0.f;
    int buf = 0;

    for (int c0 = t0; c0 < t1; c0 += CHUNK) {
        if (c0 + CHUNK < t1) {
            stage(c0 + CHUNK, buf ^ 1);
            cp_commit();
            cp_wait<1>();
        } else {
            cp_wait<0>();
        }
        __syncthreads();

        int nt = min(CHUNK, t1 - c0);
        const float* rows = s_rows + buf * (CHUNK * DD);

        if (wid < nt) {
            const float4* r4 = (const float4*)(rows + wid * DD);
            const float4* w4 = (const float4*)s_w;
            float pd = 0.f;
            #pragma unroll
            for (int j = 0; j < 6; j++) {
                int q = lane + 32 * j;
                float4 v = r4[q];
                float4 w = w4[q];
                pd += v.x * w.x + v.y * w.y + v.z * w.z + v.w * w.w;
            }
            #pragma unroll
            for (int o = 16; o > 0; o >>= 1)
                pd += __shfl_xor_sync(0xffffffffu, pd, o);
            if (lane == 0) s_scores[wid] = pd + fc5_b[0];
        }
        __syncthreads();

        float cm = -INFINITY;
        for (int t = 0; t < nt; t++) cm = fmaxf(cm, s_scores[t]);
        float nm = fmaxf(m, cm);
        float sc = (m == -INFINITY) ? 0.f : __expf(m - nm);
        acc0 *= sc; acc1 *= sc; acc2 *= sc; l *= sc;
        for (int t = 0; t < nt; t++) {
            float p = __expf(s_scores[t] - nm);
            l += p;
            acc0 += p * rows[t * DD + d0];
            acc1 += p * rows[t * DD + d1];
            acc2 += p * rows[t * DD + d2];
        }
        m = nm;
        __syncthreads();
        buf ^= 1;
    }

    float inv = 1.f / l;
    float* out = pooled + (long)blk * DD;
    out[d0] = acc0 * inv;
    out[d1] = acc1 * inv;
    out[d2] = acc2 * inv;
}

// =====================================================================
// Tensor-core GEMM (3xTF32) v4: 64x64 tile, 3-stage cp.async pipeline,
// ONE __syncthreads per k-tile. 8 warps (2m x 4n), warp tile 32x16.
// Mask-based hi/lo split. smem ~30 KB.
// Requires M % 64 == 0 (true: 4224 = 66*64).
// =====================================================================
#define KT 16
#define PAF 20
#define A_BUF (64 * PAF)
#define B_BUF (64 * PAF)

__device__ __forceinline__ void mma_tf32(float* c,
                                         uint32_t a0, uint32_t a1, uint32_t a2, uint32_t a3,
                                         uint32_t b0, uint32_t b1) {
    asm volatile(
        "mma.sync.aligned.m16n8k8.row.col.f32.tf32.tf32.f32 "
        "{%0,%1,%2,%3}, {%4,%5,%6,%7}, {%8,%9}, {%0,%1,%2,%3};"
        : "+f"(c[0]), "+f"(c[1]), "+f"(c[2]), "+f"(c[3])
        : "r"(a0), "r"(a1), "r"(a2), "r"(a3), "r"(b0), "r"(b1));
}

__global__ __launch_bounds__(256) void gemm_tc(
        const float* __restrict__ A,
        const float* __restrict__ W,
        const float* __restrict__ bias,
        const float* __restrict__ res,
        float* __restrict__ C,
        int M, int N, int K, int relu) {
    __shared__ float As[3 * A_BUF];
    __shared__ float Bs[3 * B_BUF];

    int tid  = threadIdx.x;
    int lane = tid & 31;
    int wrp  = tid >> 5;
    int wm   = wrp & 1;        // 0..1 (m)
    int wn   = wrp >> 1;       // 0..3 (n)
    int m0   = blockIdx.x * 64;
    int n0   = blockIdx.y * 64;

    int g = lane >> 2;
    int t = lane & 3;

    float acc[2][2][4];
    #pragma unroll
    for (int mi = 0; mi < 2; mi++)
        #pragma unroll
        for (int ni = 0; ni < 2; ni++)
            #pragma unroll
            for (int r = 0; r < 4; r++) acc[mi][ni][r] = 0.f;

    int lr = tid >> 2;          // 0..63
    int lk = (tid & 3) * 4;     // 0,4,8,12

    int NK = (K + KT - 1) / KT;

    auto stage = [&](int kt) {
        int buf = kt % 3;
        int k0 = kt * KT;
        int kb = (K - (k0 + lk)) * 4;
        int sb = kb < 0 ? 0 : (kb > 16 ? 16 : kb);
        int ko = k0 + lk;
        if (ko > K - 4) ko = (K - 4 < 0) ? 0 : K - 4;
        float* abuf = As + buf * A_BUF;
        float* bbuf = Bs + buf * B_BUF;
        cp_async16(abuf + lr * PAF + lk, A + (long)(m0 + lr) * K + ko, sb);
        int gn = n0 + lr;
        int wb = (gn < N) ? sb : 0;
        int gnc = (gn < N) ? gn : N - 1;
        cp_async16(bbuf + lr * PAF + lk, W + (long)gnc * K + ko, wb);
    };

    stage(0);
    cp_commit();
    if (1 < NK) { stage(1); cp_commit(); }

    for (int kt = 0; kt < NK; kt++) {
        // ensure group kt has landed
        if (kt + 1 < NK) cp_wait<1>();
        else             cp_wait<0>();
        // barrier: (a) makes buf kt visible to all warps, (b) guarantees all
        // warps are done reading buf (kt-1)%3 == (kt+2)%3 before we restage it
        __syncthreads();
        if (kt + 2 < NK) { stage(kt + 2); cp_commit(); }

        const float* abuf = As + (kt % 3) * A_BUF;
        const float* bbuf = Bs + (kt % 3) * B_BUF;

        #pragma unroll
        for (int ks = 0; ks < KT; ks += 8) {
            float ar[2][4];
            #pragma unroll
            for (int mi = 0; mi < 2; mi++) {
                int mb = wm * 32 + mi * 16;
                ar[mi][0] = abuf[(mb + g)     * PAF + ks + t];
                ar[mi][1] = abuf[(mb + g + 8) * PAF + ks + t];
                ar[mi][2] = abuf[(mb + g)     * PAF + ks + 4 + t];
                ar[mi][3] = abuf[(mb + g + 8) * PAF + ks + 4 + t];
            }
            float br[2][2];
            #pragma unroll
            for (int ni = 0; ni < 2; ni++) {
                int nb = wn * 16 + ni * 8;
                br[ni][0] = bbuf[(nb + g) * PAF + ks + t];
                br[ni][1] = bbuf[(nb + g) * PAF + ks + 4 + t];
            }
            uint32_t ahi[2][4], alo[2][4];
            #pragma unroll
            for (int mi = 0; mi < 2; mi++)
                #pragma unroll
                for (int r = 0; r < 4; r++) {
                    uint32_t h = __float_as_uint(ar[mi][r]) & 0xFFFFE000u;
                    ahi[mi][r] = h;
                    alo[mi][r] = __float_as_uint(ar[mi][r] - __uint_as_float(h));
                }
            uint32_t bhi[2][2], blo[2][2];
            #pragma unroll
            for (int ni = 0; ni < 2; ni++)
                #pragma unroll
                for (int r = 0; r < 2; r++) {
                    uint32_t h = __float_as_uint(br[ni][r]) & 0xFFFFE000u;
                    bhi[ni][r] = h;
                    blo[ni][r] = __float_as_uint(br[ni][r] - __uint_as_float(h));
                }
            #pragma unroll
            for (int mi = 0; mi < 2; mi++) {
                #pragma unroll
                for (int ni = 0; ni < 2; ni++) {
                    float* c = acc[mi][ni];
                    mma_tf32(c, ahi[mi][0], ahi[mi][1], ahi[mi][2], ahi[mi][3],
                             bhi[ni][0], bhi[ni][1]);
                    mma_tf32(c, ahi[mi][0], ahi[mi][1], ahi[mi][2], ahi[mi][3],
                             blo[ni][0], blo[ni][1]);
                    mma_tf32(c, alo[mi][0], alo[mi][1], alo[mi][2], alo[mi][3],
                             bhi[ni][0], bhi[ni][1]);
                }
            }
        }
    }

    #pragma unroll
    for (int mi = 0; mi < 2; mi++) {
        int row0 = m0 + wm * 32 + mi * 16 + g;
        int row1 = row0 + 8;
        #pragma unroll
        for (int ni = 0; ni < 2; ni++) {
            int col = n0 + wn * 16 + ni * 8 + 2 * t;
            if (col >= N) continue;
            float* c = acc[mi][ni];
            float2 bv = make_float2(0.f, 0.f);
            if (bias) bv = *(const float2*)(bias + col);
            float2 v0 = make_float2(c[0] + bv.x, c[1] + bv.y);
            float2 v1 = make_float2(c[2] + bv.x, c[3] + bv.y);
            if (res) {
                float2 r0 = *(const float2*)(res + (long)row0 * N + col);
                float2 r1 = *(const float2*)(res + (long)row1 * N + col);
                v0.x += r0.x; v0.y += r0.y;
                v1.x += r1.x; v1.y += r1.y;
            }
            if (relu) {
                v0.x = fmaxf(v0.x, 0.f); v0.y = fmaxf(v0.y, 0.f);
                v1.x = fmaxf(v1.x, 0.f); v1.y = fmaxf(v1.y, 0.f);
            }
            *(float2*)(C + (long)row0 * N + col) = v0;
            *(float2*)(C + (long)row1 * N + col) = v1;
        }
    }
}

// =====================================================================
// attn v5 (reverted to R13 best): Q,K,V in smem; one query per warp;
// 4-lane-group dots; float4 PV. Grid (B, 2), block 544 = 17 warps.
// =====================================================================
#define AP 212                       // row pitch (200 data + 12 zero pad)
__global__ __launch_bounds__(544) void attn_kernel(
        const float* __restrict__ qkv,
        float* __restrict__ att) {
    extern __shared__ float smA[];
    float* sq = smA;                  // [33][212]
    float* sk = sq + SS * AP;         // [33][212]
    float* sv = sk + SS * AP;         // [33][212]

    int b = blockIdx.x, h = blockIdx.y;
    int tid = threadIdx.x, lane = tid & 31, w = tid >> 5;
    const float* base = qkv + (long)b * SS * 3 * DM;

    for (int idx = tid; idx < SS * 50; idx += 544) {
        int r = idx / 50, c = idx % 50;
        const float* src = base + (long)r * 3 * DM + c * 4;
        *(float4*)(sq + r * AP + c * 4) = *(const float4*)(src);
        *(float4*)(sk + r * AP + c * 4) = *(const float4*)(src + DM);
        *(float4*)(sv + r * AP + c * 4) = *(const float4*)(src + 2 * DM);
    }
    for (int idx = tid; idx < SS * 12; idx += 544) {
        int r = idx / 12, c = 200 + idx % 12;
        sq[r * AP + c] = 0.f;
        sk[r * AP + c] = 0.f;
        sv[r * AP + c] = 0.f;
    }
    __syncthreads();

    int i = h * 17 + w;
    if (i >= SS) return;

    int g = lane >> 2;
    int t = lane & 3;

    const float scale = 0.0707106781186547524f;
    const float* qrow = sq + i * AP;

    int d1 = 128 + 4 * lane;
    int d1c = (d1 > 208) ? 208 : d1;
    float4 o0 = make_float4(0.f, 0.f, 0.f, 0.f);
    float4 o1 = make_float4(0.f, 0.f, 0.f, 0.f);
    float mx = -INFINITY, l = 0.f;

    for (int j0 = 0; j0 < SS; j0 += 8) {
        int j = j0 + g;
        bool jv = (j < SS);
        const float* krow = sk + (jv ? j : 0) * AP;
        float p = 0.f;
        #pragma unroll
        for (int ii = 0; ii < 13; ii++) {
            float4 kx = *(const float4*)(krow + 4 * t + 16 * ii);
            float4 qx = *(const float4*)(qrow + 4 * t + 16 * ii);
            p += qx.x * kx.x + qx.y * kx.y + qx.z * kx.z + qx.w * kx.w;
        }
        p += __shfl_xor_sync(0xffffffffu, p, 1);
        p += __shfl_xor_sync(0xffffffffu, p, 2);
        p = jv ? p * scale : -INFINITY;

        float s[8];
        #pragma unroll
        for (int jj = 0; jj < 8; jj++)
            s[jj] = __shfl_sync(0xffffffffu, p, jj << 2);

        float cm = s[0];
        #pragma unroll
        for (int jj = 1; jj < 8; jj++) cm = fmaxf(cm, s[jj]);
        float nm = fmaxf(mx, cm);
        float sc = __expf(mx - nm);
        l *= sc;
        o0.x *= sc; o0.y *= sc; o0.z *= sc; o0.w *= sc;
        o1.x *= sc; o1.y *= sc; o1.z *= sc; o1.w *= sc;
        mx = nm;

        float pe[8];
        #pragma unroll
        for (int jj = 0; jj < 8; jj++) {
            pe[jj] = __expf(s[jj] - nm);
            l += pe[jj];
        }
        #pragma unroll
        for (int jj = 0; jj < 8; jj++) {
            int jp = j0 + jj;
            if (jp >= SS) break;
            const float* vrow = sv + jp * AP;
            float4 v0 = *(const float4*)(vrow + 4 * lane);
            float4 v1 = *(const float4*)(vrow + d1c);
            float pj = pe[jj];
            o0.x += pj * v0.x; o0.y += pj * v0.y; o0.z += pj * v0.z; o0.w += pj * v0.w;
            o1.x += pj * v1.x; o1.y += pj * v1.y; o1.z += pj * v1.z; o1.w += pj * v1.w;
        }
    }

    float inv = 1.f / l;
    float* outr = att + ((long)b * SS + i) * DM;
    o0.x *= inv; o0.y *= inv; o0.z *= inv; o0.w *= inv;
    *(float4*)(outr + 4 * lane) = o0;
    if (d1 + 3 < DM) {
        o1.x *= inv; o1.y *= inv; o1.z *= inv; o1.w *= inv;
        *(float4*)(outr + d1) = o1;
    }
}

// =====================================================================
// LayerNorm over DM=200, one warp per row
// =====================================================================
__global__ void ln_kernel(const float* __restrict__ x,
                          const float* __restrict__ g,
                          const float* __restrict__ bta,
                          float* __restrict__ y, int M) {
    int row = blockIdx.x * 8 + (threadIdx.x >> 5);
    int lane = threadIdx.x & 31;
    if (row >= M) return;
    const float* xr = x + (long)row * DM;
    float vals[7];
    float s = 0.f;
    #pragma unroll
    for (int i = 0; i < 7; i++) {
        int d = lane + 32 * i;
        vals[i] = (d < DM) ? xr[d] : 0.f;
        s += vals[i];
    }
    #pragma unroll
    for (int o = 16; o > 0; o >>= 1) s += __shfl_xor_sync(0xffffffffu, s, o);
    float mean = s / (float)DM;
    float vs = 0.f;
    #pragma unroll
    for (int i = 0; i < 7; i++) {
        int d = lane + 32 * i;
        if (d < DM) { float tt = vals[i] - mean; vs += tt * tt; }
    }
    #pragma unroll
    for (int o = 16; o > 0; o >>= 1) vs += __shfl_xor_sync(0xffffffffu, vs, o);
    float inv = rsqrtf(vs / (float)DM + 1e-5f);
    float* yr = y + (long)row * DM;
    #pragma unroll
    for (int i = 0; i < 7; i++) {
        int d = lane + 32 * i;
        if (d < DM) yr[d] = (vals[i] - mean) * inv * g[d] + bta[d];
    }
}

// =====================================================================
// Final head: warp-per-output with shuffle reduction
// =====================================================================
__global__ void head_kernel(const float* __restrict__ x,
                            const float* __restrict__ fcw,
                            const float* __restrict__ fcb,
                            float* __restrict__ out) {
    int b = blockIdx.x;
    int lane = threadIdx.x & 31, wid = threadIdx.x >> 5;
    const float* x0 = x + (long)b * SS * DM;
    for (int oid = wid; oid < (SS - 1) * 2; oid += 8) {
        int srow = 1 + (oid >> 1), c = oid & 1;
        const float* xs = x0 + (long)srow * DM;
        const float* w  = fcw + c * (2 * DM);
        float d = 0.f;
        #pragma unroll
        for (int i = 0; i < 7; i++) {
            int k = lane + 32 * i;
            if (k < DM) d += w[k] * x0[k] + w[DM + k] * xs[k];
        }
        #pragma unroll
        for (int o = 16; o > 0; o >>= 1)
            d += __shfl_xor_sync(0xffffffffu, d, o);
        if (lane == 0)
            out[((long)b * (SS - 1) + (srow - 1)) * 2 + c] = d + fcb[c];
    }
}

// =====================================================================
// Launch
// =====================================================================
extern "C" void kernel_launch(void* const* d_in, const int* in_sizes, int n_in,
                              void* d_out, int out_size) {
    const float* hidden     = (const float*)d_in[0];
    const int*   cidx       = (const int*)  d_in[1];
    const float* fc5_w      = (const float*)d_in[2];
    const float* fc5_b      = (const float*)d_in[3];
    const float* fc1_w      = (const float*)d_in[4];
    const float* fc1_b      = (const float*)d_in[5];
    const float* attn_in_w  = (const float*)d_in[6];
    const float* attn_in_b  = (const float*)d_in[7];
    const float* attn_out_w = (const float*)d_in[8];
    const float* attn_out_b = (const float*)d_in[9];
    const float* ln1_g      = (const float*)d_in[10];
    const float* ln1_b      = (const float*)d_in[11];
    const float* lin1_w     = (const float*)d_in[12];
    const float* lin1_b     = (const float*)d_in[13];
    const float* lin2_w     = (const float*)d_in[14];
    const float* lin2_b     = (const float*)d_in[15];
    const float* ln2_g      = (const float*)d_in[16];
    const float* ln2_b      = (const float*)d_in[17];
    const float* fc_w       = (const float*)d_in[18];
    const float* fc_b       = (const float*)d_in[19];
    float* out = (float*)d_out;

    float *pooled, *x0, *qkv, *att, *y, *x1, *f, *x2;
    cudaGetSymbolAddress((void**)&pooled, g_pooled);
    cudaGetSymbolAddress((void**)&x0,  g_x0);
    cudaGetSymbolAddress((void**)&qkv, g_qkv);
    cudaGetSymbolAddress((void**)&att, g_att);
    cudaGetSymbolAddress((void**)&y,   g_y);
    cudaGetSymbolAddress((void**)&x1,  g_x1);
    cudaGetSymbolAddress((void**)&f,   g_f);
    cudaGetSymbolAddress((void**)&x2,  g_x2);

    const int pool_smem = (DD + 2 * CHUNK * DD + CHUNK) * (int)sizeof(float);  // ~52.3 KB
    const int attn_smem = 3 * SS * AP * (int)sizeof(float);                    // ~84 KB
    cudaFuncSetAttribute(pool_kernel, cudaFuncAttributeMaxDynamicSharedMemorySize, pool_smem);
    cudaFuncSetAttribute(attn_kernel, cudaFuncAttributeMaxDynamicSharedMemorySize, attn_smem);

    // 1. fused scores + segment softmax + pooling (single HBM pass, pipelined)
    pool_kernel<<<BB * SS, 256, pool_smem>>>(hidden, cidx, fc5_w, fc5_b, pooled);

    // 2. fc1: [4224,768] @ [768,200]^T  (3xTF32, 3-stage pipeline, 1 bar/k-tile)
    gemm_tc<<<dim3(66, 4), 256>>>(pooled, fc1_w, fc1_b, nullptr, x0, ROWS, DM, DD, 0);

    // 3. qkv: [4224,200] @ [200,600]^T
    gemm_tc<<<dim3(66, 10), 256>>>(x0, attn_in_w, attn_in_b, nullptr, qkv, ROWS, 3 * DM, DM, 0);

    // 4. attention: smem-staged, one query per warp, grid (128,2) x 544
    attn_kernel<<<dim3(BB, 2), 544, attn_smem>>>(qkv, att);

    // 5. out-proj + residual -> LN1
    gemm_tc<<<dim3(66, 4), 256>>>(att, attn_out_w, attn_out_b, x0, y, ROWS, DM, DM, 0);
    ln_kernel<<<(ROWS + 7) / 8, 256>>>(y, ln1_g, ln1_b, x1, ROWS);

    // 6. FFN: relu(x@lin1^T) @ lin2^T + residual -> LN2
    gemm_tc<<<dim3(66, 4), 256>>>(x1, lin1_w, lin1_b, nullptr, f, ROWS, DM, DM, 1);
    gemm_tc<<<dim3(66, 4), 256>>>(f, lin2_w, lin2_b, x1, y, ROWS, DM, DM, 0);
    ln_kernel<<<(ROWS + 7) / 8, 256>>>(y, ln2_g, ln2_b, x2, ROWS);

    // 7. classifier head
    head_kernel<<<BB, 256>>>(x2, fc_w, fc_b, out);
}

// round 16
// speedup vs baseline: 1.0359x; 1.0359x over previous
#include <cuda_runtime.h>
#include <math.h>
#include <stdint.h>

#define BB 128
#define LL 512
#define DD 768
#define JJ 32
#define SS 33      // J+1 segments
#define DM 200
#define DF 200
#define ROWS (BB*SS)   // 4224
#define CHUNK 8

// ---------------- scratch (no allocations allowed) ----------------
__device__ float g_pooled[ROWS * DD];   // [B*S, 768]
__device__ float g_x0[ROWS * DM];       // fc1 output
__device__ float g_qkv[ROWS * 3 * DM];  // qkv
__device__ float g_att[ROWS * DM];      // attention output (pre out-proj)
__device__ float g_y[ROWS * DM];        // pre-LN buffer
__device__ float g_x1[ROWS * DM];       // post-LN1
__device__ float g_f[ROWS * DM];        // ffn hidden
__device__ float g_x2[ROWS * DM];       // post-LN2

// ---------------- cp.async helpers ----------------
__device__ __forceinline__ void cp_async16(float* smem_dst, const float* gsrc, int src_bytes) {
    uint32_t s = (uint32_t)__cvta_generic_to_shared(smem_dst);
    asm volatile("cp.async.cg.shared.global [%0], [%1], 16, %2;"
                 :: "r"(s), "l"(gsrc), "r"(src_bytes));
}
__device__ __forceinline__ void cp_commit() {
    asm volatile("cp.async.commit_group;");
}
template <int N>
__device__ __forceinline__ void cp_wait() {
    asm volatile("cp.async.wait_group %0;" :: "n"(N));
}

// =====================================================================
// Kernel 1: fused fc5 scores + per-segment softmax + pooling.
// cp.async double-buffered, CHUNK=8, ~52 KB smem.
// =====================================================================
__global__ __launch_bounds__(256) void pool_kernel(
        const float* __restrict__ hidden,
        const int* __restrict__ cidx,
        const float* __restrict__ fc5_w,
        const float* __restrict__ fc5_b,
        float* __restrict__ pooled) {
    extern __shared__ float sm[];
    float* s_w      = sm;                        // [768]
    float* s_rows   = sm + DD;                   // [2][CHUNK][768]
    float* s_scores = s_rows + 2 * CHUNK * DD;   // [CHUNK]

    int blk = blockIdx.x;
    int b = blk / SS, s = blk % SS;
    int t0 = (s == 0)  ? 0  : cidx[b * JJ + s - 1];
    int t1 = (s == JJ) ? LL : cidx[b * JJ + s];

    int tid = threadIdx.x;
    int lane = tid & 31, wid = tid >> 5;

    const float* hb = hidden + (long)b * LL * DD;

    auto stage = [&](int c, int buf) {
        int nt = min(CHUNK, t1 - c);
        float* dst = s_rows + buf * (CHUNK * DD);
        int total = nt * (DD / 4);
        for (int idx = tid; idx < total; idx += 256) {
            int tok = idx / (DD / 4);
            int q   = idx % (DD / 4);
            cp_async16(dst + tok * DD + q * 4,
                       hb + (long)(c + tok) * DD + q * 4, 16);
        }
    };

    for (int i = tid; i < DD / 4; i += 256)
        ((float4*)s_w)[i] = ((const float4*)fc5_w)[i];
    stage(t0, 0);
    cp_commit();

    const int d0 = tid, d1 = tid + 256, d2 = tid + 512;
    float acc0 = 0.f, acc1 = 0.f, acc2 = 0.f;
    float m = -INFINITY, l = 0.f;
    int buf = 0;

    for (int c0 = t0; c0 < t1; c0 += CHUNK) {
        if (c0 + CHUNK < t1) {
            stage(c0 + CHUNK, buf ^ 1);
            cp_commit();
            cp_wait<1>();
        } else {
            cp_wait<0>();
        }
        __syncthreads();

        int nt = min(CHUNK, t1 - c0);
        const float* rows = s_rows + buf * (CHUNK * DD);

        if (wid < nt) {
            const float4* r4 = (const float4*)(rows + wid * DD);
            const float4* w4 = (const float4*)s_w;
            float pd = 0.f;
            #pragma unroll
            for (int j = 0; j < 6; j++) {
                int q = lane + 32 * j;
                float4 v = r4[q];
                float4 w = w4[q];
                pd += v.x * w.x + v.y * w.y + v.z * w.z + v.w * w.w;
            }
            #pragma unroll
            for (int o = 16; o > 0; o >>= 1)
                pd += __shfl_xor_sync(0xffffffffu, pd, o);
            if (lane == 0) s_scores[wid] = pd + fc5_b[0];
        }
        __syncthreads();

        float cm = -INFINITY;
        for (int t = 0; t < nt; t++) cm = fmaxf(cm, s_scores[t]);
        float nm = fmaxf(m, cm);
        float sc = (m == -INFINITY) ? 0.f : __expf(m - nm);
        acc0 *= sc; acc1 *= sc; acc2 *= sc; l *= sc;
        for (int t = 0; t < nt; t++) {
            float p = __expf(s_scores[t] - nm);
            l += p;
            acc0 += p * rows[t * DD + d0];
            acc1 += p * rows[t * DD + d1];
            acc2 += p * rows[t * DD + d2];
        }
        m = nm;
        __syncthreads();
        buf ^= 1;
    }

    float inv = 1.f / l;
    float* out = pooled + (long)blk * DD;
    out[d0] = acc0 * inv;
    out[d1] = acc1 * inv;
    out[d2] = acc2 * inv;
}

// =====================================================================
// Tensor-core GEMM (3xTF32): 64x64 tile, 2-stage cp.async double buffer
// (R14 measured-best). 8 warps (2m x 4n), warp tile 32x16.
// Mask-based hi/lo split. smem ~20 KB.
// Requires M % 64 == 0 (true: 4224 = 66*64).
// =====================================================================
#define KT 16
#define PAF 20
#define A_BUF (64 * PAF)
#define B_BUF (64 * PAF)

__device__ __forceinline__ void mma_tf32(float* c,
                                         uint32_t a0, uint32_t a1, uint32_t a2, uint32_t a3,
                                         uint32_t b0, uint32_t b1) {
    asm volatile(
        "mma.sync.aligned.m16n8k8.row.col.f32.tf32.tf32.f32 "
        "{%0,%1,%2,%3}, {%4,%5,%6,%7}, {%8,%9}, {%0,%1,%2,%3};"
        : "+f"(c[0]), "+f"(c[1]), "+f"(c[2]), "+f"(c[3])
        : "r"(a0), "r"(a1), "r"(a2), "r"(a3), "r"(b0), "r"(b1));
}

__global__ __launch_bounds__(256) void gemm_tc(
        const float* __restrict__ A,
        const float* __restrict__ W,
        const float* __restrict__ bias,
        const float* __restrict__ res,
        float* __restrict__ C,
        int M, int N, int K, int relu) {
    __shared__ float As[2 * A_BUF];
    __shared__ float Bs[2 * B_BUF];

    int tid  = threadIdx.x;
    int lane = tid & 31;
    int wrp  = tid >> 5;
    int wm   = wrp & 1;        // 0..1 (m)
    int wn   = wrp >> 1;       // 0..3 (n)
    int m0   = blockIdx.x * 64;
    int n0   = blockIdx.y * 64;

    int g = lane >> 2;
    int t = lane & 3;

    float acc[2][2][4];
    #pragma unroll
    for (int mi = 0; mi < 2; mi++)
        #pragma unroll
        for (int ni = 0; ni < 2; ni++)
            #pragma unroll
            for (int r = 0; r < 4; r++) acc[mi][ni][r] = 0.f;

    int lr = tid >> 2;          // 0..63
    int lk = (tid & 3) * 4;     // 0,4,8,12

    int NK = (K + KT - 1) / KT;

    auto stage = [&](int kt, int buf) {
        int k0 = kt * KT;
        int kb = (K - (k0 + lk)) * 4;
        int sb = kb < 0 ? 0 : (kb > 16 ? 16 : kb);
        int ko = k0 + lk;
        if (ko > K - 4) ko = (K - 4 < 0) ? 0 : K - 4;
        float* abuf = As + buf * A_BUF;
        float* bbuf = Bs + buf * B_BUF;
        cp_async16(abuf + lr * PAF + lk, A + (long)(m0 + lr) * K + ko, sb);
        int gn = n0 + lr;
        int wb = (gn < N) ? sb : 0;
        int gnc = (gn < N) ? gn : N - 1;
        cp_async16(bbuf + lr * PAF + lk, W + (long)gnc * K + ko, wb);
    };

    stage(0, 0);
    cp_commit();

    for (int kt = 0; kt < NK; kt++) {
        if (kt + 1 < NK) {
            stage(kt + 1, (kt + 1) & 1);
            cp_commit();
            cp_wait<1>();
        } else {
            cp_wait<0>();
        }
        __syncthreads();

        const float* abuf = As + (kt & 1) * A_BUF;
        const float* bbuf = Bs + (kt & 1) * B_BUF;

        #pragma unroll
        for (int ks = 0; ks < KT; ks += 8) {
            float ar[2][4];
            #pragma unroll
            for (int mi = 0; mi < 2; mi++) {
                int mb = wm * 32 + mi * 16;
                ar[mi][0] = abuf[(mb + g)     * PAF + ks + t];
                ar[mi][1] = abuf[(mb + g + 8) * PAF + ks + t];
                ar[mi][2] = abuf[(mb + g)     * PAF + ks + 4 + t];
                ar[mi][3] = abuf[(mb + g + 8) * PAF + ks + 4 + t];
            }
            float br[2][2];
            #pragma unroll
            for (int ni = 0; ni < 2; ni++) {
                int nb = wn * 16 + ni * 8;
                br[ni][0] = bbuf[(nb + g) * PAF + ks + t];
                br[ni][1] = bbuf[(nb + g) * PAF + ks + 4 + t];
            }
            uint32_t ahi[2][4], alo[2][4];
            #pragma unroll
            for (int mi = 0; mi < 2; mi++)
                #pragma unroll
                for (int r = 0; r < 4; r++) {
                    uint32_t h = __float_as_uint(ar[mi][r]) & 0xFFFFE000u;
                    ahi[mi][r] = h;
                    alo[mi][r] = __float_as_uint(ar[mi][r] - __uint_as_float(h));
                }
            uint32_t bhi[2][2], blo[2][2];
            #pragma unroll
            for (int ni = 0; ni < 2; ni++)
                #pragma unroll
                for (int r = 0; r < 2; r++) {
                    uint32_t h = __float_as_uint(br[ni][r]) & 0xFFFFE000u;
                    bhi[ni][r] = h;
                    blo[ni][r] = __float_as_uint(br[ni][r] - __uint_as_float(h));
                }
            #pragma unroll
            for (int mi = 0; mi < 2; mi++) {
                #pragma unroll
                for (int ni = 0; ni < 2; ni++) {
                    float* c = acc[mi][ni];
                    mma_tf32(c, ahi[mi][0], ahi[mi][1], ahi[mi][2], ahi[mi][3],
                             bhi[ni][0], bhi[ni][1]);
                    mma_tf32(c, ahi[mi][0], ahi[mi][1], ahi[mi][2], ahi[mi][3],
                             blo[ni][0], blo[ni][1]);
                    mma_tf32(c, alo[mi][0], alo[mi][1], alo[mi][2], alo[mi][3],
                             bhi[ni][0], bhi[ni][1]);
                }
            }
        }
        __syncthreads();
    }

    #pragma unroll
    for (int mi = 0; mi < 2; mi++) {
        int row0 = m0 + wm * 32 + mi * 16 + g;
        int row1 = row0 + 8;
        #pragma unroll
        for (int ni = 0; ni < 2; ni++) {
            int col = n0 + wn * 16 + ni * 8 + 2 * t;
            if (col >= N) continue;
            float* c = acc[mi][ni];
            float2 bv = make_float2(0.f, 0.f);
            if (bias) bv = *(const float2*)(bias + col);
            float2 v0 = make_float2(c[0] + bv.x, c[1] + bv.y);
            float2 v1 = make_float2(c[2] + bv.x, c[3] + bv.y);
            if (res) {
                float2 r0 = *(const float2*)(res + (long)row0 * N + col);
                float2 r1 = *(const float2*)(res + (long)row1 * N + col);
                v0.x += r0.x; v0.y += r0.y;
                v1.x += r1.x; v1.y += r1.y;
            }
            if (relu) {
                v0.x = fmaxf(v0.x, 0.f); v0.y = fmaxf(v0.y, 0.f);
                v1.x = fmaxf(v1.x, 0.f); v1.y = fmaxf(v1.y, 0.f);
            }
            *(float2*)(C + (long)row0 * N + col) = v0;
            *(float2*)(C + (long)row1 * N + col) = v1;
        }
    }
}

// =====================================================================
// attn v7: two-pass softmax (no online rescaling -> far fewer live regs),
// one query per warp, scores in smem, 4-lane-group dots, float4 PV.
// Grid (B, 2), block 544 = 17 warps, __launch_bounds__(544, 2) to force
// 2 blocks/SM (34 warps, ~53% occupancy ceiling).
// =====================================================================
#define AP 212                       // qkv row pitch (200 data + 12 zero pad)
#define SPP 36                       // score row pitch
__global__ __launch_bounds__(544, 2) void attn_kernel(
        const float* __restrict__ qkv,
        float* __restrict__ att) {
    extern __shared__ float smA[];
    float* sq = smA;                  // [33][212]
    float* sk = sq + SS * AP;         // [33][212]
    float* sv = sk + SS * AP;         // [33][212]
    float* sp = sv + SS * AP;         // [17][36] per-warp score rows

    int b = blockIdx.x, h = blockIdx.y;
    int tid = threadIdx.x, lane = tid & 31, w = tid >> 5;
    const float* base = qkv + (long)b * SS * 3 * DM;

    for (int idx = tid; idx < SS * 50; idx += 544) {
        int r = idx / 50, c = idx % 50;
        const float* src = base + (long)r * 3 * DM + c * 4;
        *(float4*)(sq + r * AP + c * 4) = *(const float4*)(src);
        *(float4*)(sk + r * AP + c * 4) = *(const float4*)(src + DM);
        *(float4*)(sv + r * AP + c * 4) = *(const float4*)(src + 2 * DM);
    }
    for (int idx = tid; idx < SS * 12; idx += 544) {
        int r = idx / 12, c = 200 + idx % 12;
        sq[r * AP + c] = 0.f;
        sk[r * AP + c] = 0.f;
        sv[r * AP + c] = 0.f;
    }
    __syncthreads();

    int i = h * 17 + w;               // query index
    if (i >= SS) return;

    int g = lane >> 2;                // key group 0..7
    int t = lane & 3;                 // lane in group
    const float scale = 0.0707106781186547524f;   // 1/sqrt(200)
    const float* qrow = sq + i * AP;
    float* sprow = sp + w * SPP;

    // ---- Phase A: all 33 scores -> smem ----
    for (int j0 = 0; j0 < SS; j0 += 8) {        // 0,8,16,24,32
        int j = j0 + g;
        bool jv = (j < SS);
        const float* krow = sk + (jv ? j : 0) * AP;
        float p = 0.f;
        #pragma unroll
        for (int ii = 0; ii < 13; ii++) {
            float4 kx = *(const float4*)(krow + 4 * t + 16 * ii);
            float4 qx = *(const float4*)(qrow + 4 * t + 16 * ii);
            p += qx.x * kx.x + qx.y * kx.y + qx.z * kx.z + qx.w * kx.w;
        }
        p += __shfl_xor_sync(0xffffffffu, p, 1);
        p += __shfl_xor_sync(0xffffffffu, p, 2);
        if (t == 0 && jv) sprow[j] = p * scale;
    }
    __syncwarp();

    // ---- softmax over 33 values (warp-collective) ----
    {
        float v0 = sprow[lane];                           // lanes 0..31
        float v1 = (lane == 0) ? sprow[32] : -INFINITY;   // the 33rd
        float mx = fmaxf(v0, v1);
        #pragma unroll
        for (int o = 16; o > 0; o >>= 1)
            mx = fmaxf(mx, __shfl_xor_sync(0xffffffffu, mx, o));
        float e0 = __expf(v0 - mx);
        float e1 = (lane == 0) ? __expf(v1 - mx) : 0.f;
        float sum = e0 + e1;
        #pragma unroll
        for (int o = 16; o > 0; o >>= 1)
            sum += __shfl_xor_sync(0xffffffffu, sum, o);
        float inv = 1.f / sum;
        sprow[lane] = e0 * inv;
        if (lane == 0) sprow[32] = e1 * inv;
    }
    __syncwarp();

    // ---- Phase B: single PV pass (probabilities already normalized) ----
    int d1 = 128 + 4 * lane;
    int d1c = (d1 > 208) ? 208 : d1;  // clamp into zeroed pad
    float4 o0 = make_float4(0.f, 0.f, 0.f, 0.f);
    float4 o1 = make_float4(0.f, 0.f, 0.f, 0.f);
    #pragma unroll 11
    for (int j = 0; j < SS; j++) {
        float pj = sprow[j];          // warp-uniform broadcast
        const float* vrow = sv + j * AP;
        float4 v0 = *(const float4*)(vrow + 4 * lane);
        float4 v1 = *(const float4*)(vrow + d1c);
        o0.x += pj * v0.x; o0.y += pj * v0.y; o0.z += pj * v0.z; o0.w += pj * v0.w;
        o1.x += pj * v1.x; o1.y += pj * v1.y; o1.z += pj * v1.z; o1.w += pj * v1.w;
    }

    float* outr = att + ((long)b * SS + i) * DM;
    *(float4*)(outr + 4 * lane) = o0;
    if (d1 + 3 < DM)                  // lanes 0..17 (d1 <= 196)
        *(float4*)(outr + d1) = o1;
}

// =====================================================================
// LayerNorm over DM=200, one warp per row
// =====================================================================
__global__ void ln_kernel(const float* __restrict__ x,
                          const float* __restrict__ g,
                          const float* __restrict__ bta,
                          float* __restrict__ y, int M) {
    int row = blockIdx.x * 8 + (threadIdx.x >> 5);
    int lane = threadIdx.x & 31;
    if (row >= M) return;
    const float* xr = x + (long)row * DM;
    float vals[7];
    float s = 0.f;
    #pragma unroll
    for (int i = 0; i < 7; i++) {
        int d = lane + 32 * i;
        vals[i] = (d < DM) ? xr[d] : 0.f;
        s += vals[i];
    }
    #pragma unroll
    for (int o = 16; o > 0; o >>= 1) s += __shfl_xor_sync(0xffffffffu, s, o);
    float mean = s / (float)DM;
    float vs = 0.f;
    #pragma unroll
    for (int i = 0; i < 7; i++) {
        int d = lane + 32 * i;
        if (d < DM) { float tt = vals[i] - mean; vs += tt * tt; }
    }
    #pragma unroll
    for (int o = 16; o > 0; o >>= 1) vs += __shfl_xor_sync(0xffffffffu, vs, o);
    float inv = rsqrtf(vs / (float)DM + 1e-5f);
    float* yr = y + (long)row * DM;
    #pragma unroll
    for (int i = 0; i < 7; i++) {
        int d = lane + 32 * i;
        if (d < DM) yr[d] = (vals[i] - mean) * inv * g[d] + bta[d];
    }
}

// =====================================================================
// Final head: warp-per-output with shuffle reduction
// =====================================================================
__global__ void head_kernel(const float* __restrict__ x,
                            const float* __restrict__ fcw,
                            const float* __restrict__ fcb,
                            float* __restrict__ out) {
    int b = blockIdx.x;
    int lane = threadIdx.x & 31, wid = threadIdx.x >> 5;
    const float* x0 = x + (long)b * SS * DM;
    for (int oid = wid; oid < (SS - 1) * 2; oid += 8) {
        int srow = 1 + (oid >> 1), c = oid & 1;
        const float* xs = x0 + (long)srow * DM;
        const float* w  = fcw + c * (2 * DM);
        float d = 0.f;
        #pragma unroll
        for (int i = 0; i < 7; i++) {
            int k = lane + 32 * i;
            if (k < DM) d += w[k] * x0[k] + w[DM + k] * xs[k];
        }
        #pragma unroll
        for (int o = 16; o > 0; o >>= 1)
            d += __shfl_xor_sync(0xffffffffu, d, o);
        if (lane == 0)
            out[((long)b * (SS - 1) + (srow - 1)) * 2 + c] = d + fcb[c];
    }
}

// =====================================================================
// Launch
// =====================================================================
extern "C" void kernel_launch(void* const* d_in, const int* in_sizes, int n_in,
                              void* d_out, int out_size) {
    const float* hidden     = (const float*)d_in[0];
    const int*   cidx       = (const int*)  d_in[1];
    const float* fc5_w      = (const float*)d_in[2];
    const float* fc5_b      = (const float*)d_in[3];
    const float* fc1_w      = (const float*)d_in[4];
    const float* fc1_b      = (const float*)d_in[5];
    const float* attn_in_w  = (const float*)d_in[6];
    const float* attn_in_b  = (const float*)d_in[7];
    const float* attn_out_w = (const float*)d_in[8];
    const float* attn_out_b = (const float*)d_in[9];
    const float* ln1_g      = (const float*)d_in[10];
    const float* ln1_b      = (const float*)d_in[11];
    const float* lin1_w     = (const float*)d_in[12];
    const float* lin1_b     = (const float*)d_in[13];
    const float* lin2_w     = (const float*)d_in[14];
    const float* lin2_b     = (const float*)d_in[15];
    const float* ln2_g      = (const float*)d_in[16];
    const float* ln2_b      = (const float*)d_in[17];
    const float* fc_w       = (const float*)d_in[18];
    const float* fc_b       = (const float*)d_in[19];
    float* out = (float*)d_out;

    float *pooled, *x0, *qkv, *att, *y, *x1, *f, *x2;
    cudaGetSymbolAddress((void**)&pooled, g_pooled);
    cudaGetSymbolAddress((void**)&x0,  g_x0);
    cudaGetSymbolAddress((void**)&qkv, g_qkv);
    cudaGetSymbolAddress((void**)&att, g_att);
    cudaGetSymbolAddress((void**)&y,   g_y);
    cudaGetSymbolAddress((void**)&x1,  g_x1);
    cudaGetSymbolAddress((void**)&f,   g_f);
    cudaGetSymbolAddress((void**)&x2,  g_x2);

    const int pool_smem = (DD + 2 * CHUNK * DD + CHUNK) * (int)sizeof(float);      // ~52.3 KB
    const int attn_smem = (3 * SS * AP + 17 * SPP) * (int)sizeof(float);           // ~86.4 KB
    cudaFuncSetAttribute(pool_kernel, cudaFuncAttributeMaxDynamicSharedMemorySize, pool_smem);
    cudaFuncSetAttribute(attn_kernel, cudaFuncAttributeMaxDynamicSharedMemorySize, attn_smem);

    // 1. fused scores + segment softmax + pooling (single HBM pass, pipelined)
    pool_kernel<<<BB * SS, 256, pool_smem>>>(hidden, cidx, fc5_w, fc5_b, pooled);

    // 2. fc1: [4224,768] @ [768,200]^T  (3xTF32, 2-stage pipeline, 64x64)
    gemm_tc<<<dim3(66, 4), 256>>>(pooled, fc1_w, fc1_b, nullptr, x0, ROWS, DM, DD, 0);

    // 3. qkv: [4224,200] @ [200,600]^T
    gemm_tc<<<dim3(66, 10), 256>>>(x0, attn_in_w, attn_in_b, nullptr, qkv, ROWS, 3 * DM, DM, 0);

    // 4. attention: two-pass softmax, one query per warp, grid (128,2) x 544
    attn_kernel<<<dim3(BB, 2), 544, attn_smem>>>(qkv, att);

    // 5. out-proj + residual -> LN1
    gemm_tc<<<dim3(66, 4), 256>>>(att, attn_out_w, attn_out_b, x0, y, ROWS, DM, DM, 0);
    ln_kernel<<<(ROWS + 7) / 8, 256>>>(y, ln1_g, ln1_b, x1, ROWS);

    // 6. FFN: relu(x@lin1^T) @ lin2^T + residual -> LN2
    gemm_tc<<<dim3(66, 4), 256>>>(x1, lin1_w, lin1_b, nullptr, f, ROWS, DM, DM, 1);
    gemm_tc<<<dim3(66, 4), 256>>>(f, lin2_w, lin2_b, x1, y, ROWS, DM, DM, 0);
    ln_kernel<<<(ROWS + 7) / 8, 256>>>(y, ln2_g, ln2_b, x2, ROWS);

    // 7. classifier head
    head_kernel<<<BB, 256>>>(x2, fc_w, fc_b, out);
}

// round 17
// speedup vs baseline: 1.0954x; 1.0575x over previous
#include <cuda_runtime.h>
#include <math.h>
#include <stdint.h>

#define BB 128
#define LL 512
#define DD 768
#define JJ 32
#define SS 33      // J+1 segments
#define DM 200
#define DF 200
#define ROWS (BB*SS)   // 4224
#define CHUNK 8

// ---------------- scratch (no allocations allowed) ----------------
__device__ float g_pooled[ROWS * DD];   // [B*S, 768]
__device__ float g_x0[ROWS * DM];       // fc1 output
__device__ float g_qkv[ROWS * 3 * DM];  // qkv
__device__ float g_att[ROWS * DM];      // attention output (pre out-proj)
__device__ float g_y[ROWS * DM];        // pre-LN buffer
__device__ float g_x1[ROWS * DM];       // post-LN1
__device__ float g_f[ROWS * DM];        // ffn hidden
__device__ float g_x2[ROWS * DM];       // post-LN2

// ---------------- cp.async helpers ----------------
__device__ __forceinline__ void cp_async16(float* smem_dst, const float* gsrc, int src_bytes) {
    uint32_t s = (uint32_t)__cvta_generic_to_shared(smem_dst);
    asm volatile("cp.async.cg.shared.global [%0], [%1], 16, %2;"
                 :: "r"(s), "l"(gsrc), "r"(src_bytes));
}
__device__ __forceinline__ void cp_commit() {
    asm volatile("cp.async.commit_group;");
}
template <int N>
__device__ __forceinline__ void cp_wait() {
    asm volatile("cp.async.wait_group %0;" :: "n"(N));
}

// =====================================================================
// Kernel 1: fused fc5 scores + per-segment softmax + pooling.
// cp.async double-buffered, CHUNK=8, ~52 KB smem.
// =====================================================================
__global__ __launch_bounds__(256) void pool_kernel(
        const float* __restrict__ hidden,
        const int* __restrict__ cidx,
        const float* __restrict__ fc5_w,
        const float* __restrict__ fc5_b,
        float* __restrict__ pooled) {
    extern __shared__ float sm[];
    float* s_w      = sm;                        // [768]
    float* s_rows   = sm + DD;                   // [2][CHUNK][768]
    float* s_scores = s_rows + 2 * CHUNK * DD;   // [CHUNK]

    int blk = blockIdx.x;
    int b = blk / SS, s = blk % SS;
    int t0 = (s == 0)  ? 0  : cidx[b * JJ + s - 1];
    int t1 = (s == JJ) ? LL : cidx[b * JJ + s];

    int tid = threadIdx.x;
    int lane = tid & 31, wid = tid >> 5;

    const float* hb = hidden + (long)b * LL * DD;

    auto stage = [&](int c, int buf) {
        int nt = min(CHUNK, t1 - c);
        float* dst = s_rows + buf * (CHUNK * DD);
        int total = nt * (DD / 4);
        for (int idx = tid; idx < total; idx += 256) {
            int tok = idx / (DD / 4);
            int q   = idx % (DD / 4);
            cp_async16(dst + tok * DD + q * 4,
                       hb + (long)(c + tok) * DD + q * 4, 16);
        }
    };

    for (int i = tid; i < DD / 4; i += 256)
        ((float4*)s_w)[i] = ((const float4*)fc5_w)[i];
    stage(t0, 0);
    cp_commit();

    const int d0 = tid, d1 = tid + 256, d2 = tid + 512;
    float acc0 = 0.f, acc1 = 0.f, acc2 = 0.f;
    float m = -INFINITY, l = 0.f;
    int buf = 0;

    for (int c0 = t0; c0 < t1; c0 += CHUNK) {
        if (c0 + CHUNK < t1) {
            stage(c0 + CHUNK, buf ^ 1);
            cp_commit();
            cp_wait<1>();
        } else {
            cp_wait<0>();
        }
        __syncthreads();

        int nt = min(CHUNK, t1 - c0);
        const float* rows = s_rows + buf * (CHUNK * DD);

        if (wid < nt) {
            const float4* r4 = (const float4*)(rows + wid * DD);
            const float4* w4 = (const float4*)s_w;
            float pd = 0.f;
            #pragma unroll
            for (int j = 0; j < 6; j++) {
                int q = lane + 32 * j;
                float4 v = r4[q];
                float4 w = w4[q];
                pd += v.x * w.x + v.y * w.y + v.z * w.z + v.w * w.w;
            }
            #pragma unroll
            for (int o = 16; o > 0; o >>= 1)
                pd += __shfl_xor_sync(0xffffffffu, pd, o);
            if (lane == 0) s_scores[wid] = pd + fc5_b[0];
        }
        __syncthreads();

        float cm = -INFINITY;
        for (int t = 0; t < nt; t++) cm = fmaxf(cm, s_scores[t]);
        float nm = fmaxf(m, cm);
        float sc = (m == -INFINITY) ? 0.f : __expf(m - nm);
        acc0 *= sc; acc1 *= sc; acc2 *= sc; l *= sc;
        for (int t = 0; t < nt; t++) {
            float p = __expf(s_scores[t] - nm);
            l += p;
            acc0 += p * rows[t * DD + d0];
            acc1 += p * rows[t * DD + d1];
            acc2 += p * rows[t * DD + d2];
        }
        m = nm;
        __syncthreads();
        buf ^= 1;
    }

    float inv = 1.f / l;
    float* out = pooled + (long)blk * DD;
    out[d0] = acc0 * inv;
    out[d1] = acc1 * inv;
    out[d2] = acc2 * inv;
}

// =====================================================================
// Tensor-core GEMM (3xTF32): 64x64 tile, 2-stage cp.async double buffer
// (R14 measured-best). 8 warps (2m x 4n), warp tile 32x16.
// =====================================================================
#define KT 16
#define PAF 20
#define A_BUF (64 * PAF)
#define B_BUF (64 * PAF)

__device__ __forceinline__ void mma_tf32(float* c,
                                         uint32_t a0, uint32_t a1, uint32_t a2, uint32_t a3,
                                         uint32_t b0, uint32_t b1) {
    asm volatile(
        "mma.sync.aligned.m16n8k8.row.col.f32.tf32.tf32.f32 "
        "{%0,%1,%2,%3}, {%4,%5,%6,%7}, {%8,%9}, {%0,%1,%2,%3};"
        : "+f"(c[0]), "+f"(c[1]), "+f"(c[2]), "+f"(c[3])
        : "r"(a0), "r"(a1), "r"(a2), "r"(a3), "r"(b0), "r"(b1));
}

__global__ __launch_bounds__(256) void gemm_tc(
        const float* __restrict__ A,
        const float* __restrict__ W,
        const float* __restrict__ bias,
        const float* __restrict__ res,
        float* __restrict__ C,
        int M, int N, int K, int relu) {
    __shared__ float As[2 * A_BUF];
    __shared__ float Bs[2 * B_BUF];

    int tid  = threadIdx.x;
    int lane = tid & 31;
    int wrp  = tid >> 5;
    int wm   = wrp & 1;
    int wn   = wrp >> 1;
    int m0   = blockIdx.x * 64;
    int n0   = blockIdx.y * 64;

    int g = lane >> 2;
    int t = lane & 3;

    float acc[2][2][4];
    #pragma unroll
    for (int mi = 0; mi < 2; mi++)
        #pragma unroll
        for (int ni = 0; ni < 2; ni++)
            #pragma unroll
            for (int r = 0; r < 4; r++) acc[mi][ni][r] = 0.f;

    int lr = tid >> 2;
    int lk = (tid & 3) * 4;

    int NK = (K + KT - 1) / KT;

    auto stage = [&](int kt, int buf) {
        int k0 = kt * KT;
        int kb = (K - (k0 + lk)) * 4;
        int sb = kb < 0 ? 0 : (kb > 16 ? 16 : kb);
        int ko = k0 + lk;
        if (ko > K - 4) ko = (K - 4 < 0) ? 0 : K - 4;
        float* abuf = As + buf * A_BUF;
        float* bbuf = Bs + buf * B_BUF;
        cp_async16(abuf + lr * PAF + lk, A + (long)(m0 + lr) * K + ko, sb);
        int gn = n0 + lr;
        int wb = (gn < N) ? sb : 0;
        int gnc = (gn < N) ? gn : N - 1;
        cp_async16(bbuf + lr * PAF + lk, W + (long)gnc * K + ko, wb);
    };

    stage(0, 0);
    cp_commit();

    for (int kt = 0; kt < NK; kt++) {
        if (kt + 1 < NK) {
            stage(kt + 1, (kt + 1) & 1);
            cp_commit();
            cp_wait<1>();
        } else {
            cp_wait<0>();
        }
        __syncthreads();

        const float* abuf = As + (kt & 1) * A_BUF;
        const float* bbuf = Bs + (kt & 1) * B_BUF;

        #pragma unroll
        for (int ks = 0; ks < KT; ks += 8) {
            float ar[2][4];
            #pragma unroll
            for (int mi = 0; mi < 2; mi++) {
                int mb = wm * 32 + mi * 16;
                ar[mi][0] = abuf[(mb + g)     * PAF + ks + t];
                ar[mi][1] = abuf[(mb + g + 8) * PAF + ks + t];
                ar[mi][2] = abuf[(mb + g)     * PAF + ks + 4 + t];
                ar[mi][3] = abuf[(mb + g + 8) * PAF + ks + 4 + t];
            }
            float br[2][2];
            #pragma unroll
            for (int ni = 0; ni < 2; ni++) {
                int nb = wn * 16 + ni * 8;
                br[ni][0] = bbuf[(nb + g) * PAF + ks + t];
                br[ni][1] = bbuf[(nb + g) * PAF + ks + 4 + t];
            }
            uint32_t ahi[2][4], alo[2][4];
            #pragma unroll
            for (int mi = 0; mi < 2; mi++)
                #pragma unroll
                for (int r = 0; r < 4; r++) {
                    uint32_t h = __float_as_uint(ar[mi][r]) & 0xFFFFE000u;
                    ahi[mi][r] = h;
                    alo[mi][r] = __float_as_uint(ar[mi][r] - __uint_as_float(h));
                }
            uint32_t bhi[2][2], blo[2][2];
            #pragma unroll
            for (int ni = 0; ni < 2; ni++)
                #pragma unroll
                for (int r = 0; r < 2; r++) {
                    uint32_t h = __float_as_uint(br[ni][r]) & 0xFFFFE000u;
                    bhi[ni][r] = h;
                    blo[ni][r] = __float_as_uint(br[ni][r] - __uint_as_float(h));
                }
            #pragma unroll
            for (int mi = 0; mi < 2; mi++) {
                #pragma unroll
                for (int ni = 0; ni < 2; ni++) {
                    float* c = acc[mi][ni];
                    mma_tf32(c, ahi[mi][0], ahi[mi][1], ahi[mi][2], ahi[mi][3],
                             bhi[ni][0], bhi[ni][1]);
                    mma_tf32(c, ahi[mi][0], ahi[mi][1], ahi[mi][2], ahi[mi][3],
                             blo[ni][0], blo[ni][1]);
                    mma_tf32(c, alo[mi][0], alo[mi][1], alo[mi][2], alo[mi][3],
                             bhi[ni][0], bhi[ni][1]);
                }
            }
        }
        __syncthreads();
    }

    #pragma unroll
    for (int mi = 0; mi < 2; mi++) {
        int row0 = m0 + wm * 32 + mi * 16 + g;
        int row1 = row0 + 8;
        #pragma unroll
        for (int ni = 0; ni < 2; ni++) {
            int col = n0 + wn * 16 + ni * 8 + 2 * t;
            if (col >= N) continue;
            float* c = acc[mi][ni];
            float2 bv = make_float2(0.f, 0.f);
            if (bias) bv = *(const float2*)(bias + col);
            float2 v0 = make_float2(c[0] + bv.x, c[1] + bv.y);
            float2 v1 = make_float2(c[2] + bv.x, c[3] + bv.y);
            if (res) {
                float2 r0 = *(const float2*)(res + (long)row0 * N + col);
                float2 r1 = *(const float2*)(res + (long)row1 * N + col);
                v0.x += r0.x; v0.y += r0.y;
                v1.x += r1.x; v1.y += r1.y;
            }
            if (relu) {
                v0.x = fmaxf(v0.x, 0.f); v0.y = fmaxf(v0.y, 0.f);
                v1.x = fmaxf(v1.x, 0.f); v1.y = fmaxf(v1.y, 0.f);
            }
            *(float2*)(C + (long)row0 * N + col) = v0;
            *(float2*)(C + (long)row1 * N + col) = v1;
        }
    }
}

// =====================================================================
// attn v8: TWO queries per warp (K/V smem reads amortized 2x), grid (B)
// x 544 (17 warps: warp w owns queries w and w+17). Q loads hoisted
// (ii-outer loop). Two-pass softmax, scores in smem, float4 PV.
// =====================================================================
#define AP 212                       // qkv row pitch (200 data + 12 zero pad)
#define SPP 36                       // score row pitch
__global__ __launch_bounds__(544) void attn_kernel(
        const float* __restrict__ qkv,
        float* __restrict__ att) {
    extern __shared__ float smA[];
    float* sq = smA;                  // [33][212]
    float* sk = sq + SS * AP;         // [33][212]
    float* sv = sk + SS * AP;         // [33][212]
    float* sp = sv + SS * AP;         // [33][36] score rows (per query)

    int b = blockIdx.x;
    int tid = threadIdx.x, lane = tid & 31, w = tid >> 5;
    const float* base = qkv + (long)b * SS * 3 * DM;

    // stage Q,K,V (33 rows x 50 float4 each)
    for (int idx = tid; idx < SS * 50; idx += 544) {
        int r = idx / 50, c = idx % 50;
        const float* src = base + (long)r * 3 * DM + c * 4;
        *(float4*)(sq + r * AP + c * 4) = *(const float4*)(src);
        *(float4*)(sk + r * AP + c * 4) = *(const float4*)(src + DM);
        *(float4*)(sv + r * AP + c * 4) = *(const float4*)(src + 2 * DM);
    }
    for (int idx = tid; idx < SS * 12; idx += 544) {
        int r = idx / 12, c = 200 + idx % 12;
        sq[r * AP + c] = 0.f;
        sk[r * AP + c] = 0.f;
        sv[r * AP + c] = 0.f;
    }
    __syncthreads();

    int q0 = w;                        // always valid (w < 17 <= 33)
    int q1 = w + 17;                   // valid iff w < 16
    bool has1 = (q1 < SS);
    int q1c = has1 ? q1 : q0;

    int g = lane >> 2;                 // key group 0..7
    int t = lane & 3;                  // lane in group
    const float scale = 0.0707106781186547524f;   // 1/sqrt(200)

    const float* q0row = sq + q0 * AP;
    const float* q1row = sq + q1c * AP;
    float* sp0 = sp + q0 * SPP;
    float* sp1 = sp + q1c * SPP;

    // this lane's 5 key rows: j = 8c + g (c = 0..4)
    const float* kr[5];
    bool jv[5];
    #pragma unroll
    for (int c = 0; c < 5; c++) {
        int j = 8 * c + g;
        jv[c] = (j < SS);
        kr[c] = sk + (jv[c] ? j : 0) * AP;
    }

    // ---- Phase A: scores for both queries, Q loaded once per ii ----
    float pa[5], pb[5];
    #pragma unroll
    for (int c = 0; c < 5; c++) { pa[c] = 0.f; pb[c] = 0.f; }
    #pragma unroll
    for (int ii = 0; ii < 13; ii++) {
        int off = 4 * t + 16 * ii;     // 0..207 (pads zeroed)
        float4 qa = *(const float4*)(q0row + off);
        float4 qb = *(const float4*)(q1row + off);
        #pragma unroll
        for (int c = 0; c < 5; c++) {
            float4 kx = *(const float4*)(kr[c] + off);
            pa[c] += qa.x * kx.x + qa.y * kx.y + qa.z * kx.z + qa.w * kx.w;
            pb[c] += qb.x * kx.x + qb.y * kx.y + qb.z * kx.z + qb.w * kx.w;
        }
    }
    #pragma unroll
    for (int c = 0; c < 5; c++) {
        pa[c] += __shfl_xor_sync(0xffffffffu, pa[c], 1);
        pa[c] += __shfl_xor_sync(0xffffffffu, pa[c], 2);
        pb[c] += __shfl_xor_sync(0xffffffffu, pb[c], 1);
        pb[c] += __shfl_xor_sync(0xffffffffu, pb[c], 2);
        if (t == 0 && jv[c]) {
            int j = 8 * c + g;
            sp0[j] = pa[c] * scale;
            if (has1) sp1[j] = pb[c] * scale;
        }
    }
    __syncwarp();

    // ---- softmax over 33 values, per owned query row ----
    {
        float v0 = sp0[lane];
        float v1 = (lane == 0) ? sp0[32] : -INFINITY;
        float mx = fmaxf(v0, v1);
        #pragma unroll
        for (int o = 16; o > 0; o >>= 1)
            mx = fmaxf(mx, __shfl_xor_sync(0xffffffffu, mx, o));
        float e0 = __expf(v0 - mx);
        float e1 = (lane == 0) ? __expf(v1 - mx) : 0.f;
        float sum = e0 + e1;
        #pragma unroll
        for (int o = 16; o > 0; o >>= 1)
            sum += __shfl_xor_sync(0xffffffffu, sum, o);
        float inv = 1.f / sum;
        sp0[lane] = e0 * inv;
        if (lane == 0) sp0[32] = e1 * inv;
    }
    if (has1) {
        float v0 = sp1[lane];
        float v1 = (lane == 0) ? sp1[32] : -INFINITY;
        float mx = fmaxf(v0, v1);
        #pragma unroll
        for (int o = 16; o > 0; o >>= 1)
            mx = fmaxf(mx, __shfl_xor_sync(0xffffffffu, mx, o));
        float e0 = __expf(v0 - mx);
        float e1 = (lane == 0) ? __expf(v1 - mx) : 0.f;
        float sum = e0 + e1;
        #pragma unroll
        for (int o = 16; o > 0; o >>= 1)
            sum += __shfl_xor_sync(0xffffffffu, sum, o);
        float inv = 1.f / sum;
        sp1[lane] = e0 * inv;
        if (lane == 0) sp1[32] = e1 * inv;
    }
    __syncwarp();

    // ---- Phase B: one V pass serves both queries ----
    int d1 = 128 + 4 * lane;
    int d1c = (d1 > 208) ? 208 : d1;   // clamp into zeroed pad
    float4 a0 = make_float4(0.f, 0.f, 0.f, 0.f);  // q0, d-low
    float4 a1 = make_float4(0.f, 0.f, 0.f, 0.f);  // q0, d-high
    float4 b0 = make_float4(0.f, 0.f, 0.f, 0.f);  // q1, d-low
    float4 b1 = make_float4(0.f, 0.f, 0.f, 0.f);  // q1, d-high
    #pragma unroll 11
    for (int j = 0; j < SS; j++) {
        float p0 = sp0[j];
        float p1 = sp1[j];
        const float* vrow = sv + j * AP;
        float4 v0 = *(const float4*)(vrow + 4 * lane);
        float4 v1 = *(const float4*)(vrow + d1c);
        a0.x += p0 * v0.x; a0.y += p0 * v0.y; a0.z += p0 * v0.z; a0.w += p0 * v0.w;
        a1.x += p0 * v1.x; a1.y += p0 * v1.y; a1.z += p0 * v1.z; a1.w += p0 * v1.w;
        b0.x += p1 * v0.x; b0.y += p1 * v0.y; b0.z += p1 * v0.z; b0.w += p1 * v0.w;
        b1.x += p1 * v1.x; b1.y += p1 * v1.y; b1.z += p1 * v1.z; b1.w += p1 * v1.w;
    }

    float* out0 = att + ((long)b * SS + q0) * DM;
    *(float4*)(out0 + 4 * lane) = a0;
    if (d1 + 3 < DM) *(float4*)(out0 + d1) = a1;
    if (has1) {
        float* out1 = att + ((long)b * SS + q1) * DM;
        *(float4*)(out1 + 4 * lane) = b0;
        if (d1 + 3 < DM) *(float4*)(out1 + d1) = b1;
    }
}

// =====================================================================
// LayerNorm over DM=200, one warp per row
// =====================================================================
__global__ void ln_kernel(const float* __restrict__ x,
                          const float* __restrict__ g,
                          const float* __restrict__ bta,
                          float* __restrict__ y, int M) {
    int row = blockIdx.x * 8 + (threadIdx.x >> 5);
    int lane = threadIdx.x & 31;
    if (row >= M) return;
    const float* xr = x + (long)row * DM;
    float vals[7];
    float s = 0.f;
    #pragma unroll
    for (int i = 0; i < 7; i++) {
        int d = lane + 32 * i;
        vals[i] = (d < DM) ? xr[d] : 0.f;
        s += vals[i];
    }
    #pragma unroll
    for (int o = 16; o > 0; o >>= 1) s += __shfl_xor_sync(0xffffffffu, s, o);
    float mean = s / (float)DM;
    float vs = 0.f;
    #pragma unroll
    for (int i = 0; i < 7; i++) {
        int d = lane + 32 * i;
        if (d < DM) { float tt = vals[i] - mean; vs += tt * tt; }
    }
    #pragma unroll
    for (int o = 16; o > 0; o >>= 1) vs += __shfl_xor_sync(0xffffffffu, vs, o);
    float inv = rsqrtf(vs / (float)DM + 1e-5f);
    float* yr = y + (long)row * DM;
    #pragma unroll
    for (int i = 0; i < 7; i++) {
        int d = lane + 32 * i;
        if (d < DM) yr[d] = (vals[i] - mean) * inv * g[d] + bta[d];
    }
}

// =====================================================================
// Final head: warp-per-output with shuffle reduction
// =====================================================================
__global__ void head_kernel(const float* __restrict__ x,
                            const float* __restrict__ fcw,
                            const float* __restrict__ fcb,
                            float* __restrict__ out) {
    int b = blockIdx.x;
    int lane = threadIdx.x & 31, wid = threadIdx.x >> 5;
    const float* x0 = x + (long)b * SS * DM;
    for (int oid = wid; oid < (SS - 1) * 2; oid += 8) {
        int srow = 1 + (oid >> 1), c = oid & 1;
        const float* xs = x0 + (long)srow * DM;
        const float* w  = fcw + c * (2 * DM);
        float d = 0.f;
        #pragma unroll
        for (int i = 0; i < 7; i++) {
            int k = lane + 32 * i;
            if (k < DM) d += w[k] * x0[k] + w[DM + k] * xs[k];
        }
        #pragma unroll
        for (int o = 16; o > 0; o >>= 1)
            d += __shfl_xor_sync(0xffffffffu, d, o);
        if (lane == 0)
            out[((long)b * (SS - 1) + (srow - 1)) * 2 + c] = d + fcb[c];
    }
}

// =====================================================================
// Launch
// =====================================================================
extern "C" void kernel_launch(void* const* d_in, const int* in_sizes, int n_in,
                              void* d_out, int out_size) {
    const float* hidden     = (const float*)d_in[0];
    const int*   cidx       = (const int*)  d_in[1];
    const float* fc5_w      = (const float*)d_in[2];
    const float* fc5_b      = (const float*)d_in[3];
    const float* fc1_w      = (const float*)d_in[4];
    const float* fc1_b      = (const float*)d_in[5];
    const float* attn_in_w  = (const float*)d_in[6];
    const float* attn_in_b  = (const float*)d_in[7];
    const float* attn_out_w = (const float*)d_in[8];
    const float* attn_out_b = (const float*)d_in[9];
    const float* ln1_g      = (const float*)d_in[10];
    const float* ln1_b      = (const float*)d_in[11];
    const float* lin1_w     = (const float*)d_in[12];
    const float* lin1_b     = (const float*)d_in[13];
    const float* lin2_w     = (const float*)d_in[14];
    const float* lin2_b     = (const float*)d_in[15];
    const float* ln2_g      = (const float*)d_in[16];
    const float* ln2_b      = (const float*)d_in[17];
    const float* fc_w       = (const float*)d_in[18];
    const float* fc_b       = (const float*)d_in[19];
    float* out = (float*)d_out;

    float *pooled, *x0, *qkv, *att, *y, *x1, *f, *x2;
    cudaGetSymbolAddress((void**)&pooled, g_pooled);
    cudaGetSymbolAddress((void**)&x0,  g_x0);
    cudaGetSymbolAddress((void**)&qkv, g_qkv);
    cudaGetSymbolAddress((void**)&att, g_att);
    cudaGetSymbolAddress((void**)&y,   g_y);
    cudaGetSymbolAddress((void**)&x1,  g_x1);
    cudaGetSymbolAddress((void**)&f,   g_f);
    cudaGetSymbolAddress((void**)&x2,  g_x2);

    const int pool_smem = (DD + 2 * CHUNK * DD + CHUNK) * (int)sizeof(float);      // ~52.3 KB
    const int attn_smem = (3 * SS * AP + SS * SPP) * (int)sizeof(float);           // ~88.7 KB
    cudaFuncSetAttribute(pool_kernel, cudaFuncAttributeMaxDynamicSharedMemorySize, pool_smem);
    cudaFuncSetAttribute(attn_kernel, cudaFuncAttributeMaxDynamicSharedMemorySize, attn_smem);

    // 1. fused scores + segment softmax + pooling (single HBM pass, pipelined)
    pool_kernel<<<BB * SS, 256, pool_smem>>>(hidden, cidx, fc5_w, fc5_b, pooled);

    // 2. fc1: [4224,768] @ [768,200]^T  (3xTF32, 2-stage pipeline, 64x64)
    gemm_tc<<<dim3(66, 4), 256>>>(pooled, fc1_w, fc1_b, nullptr, x0, ROWS, DM, DD, 0);

    // 3. qkv: [4224,200] @ [200,600]^T
    gemm_tc<<<dim3(66, 10), 256>>>(x0, attn_in_w, attn_in_b, nullptr, qkv, ROWS, 3 * DM, DM, 0);

    // 4. attention: 2 queries/warp, grid (128) x 544
    attn_kernel<<<BB, 544, attn_smem>>>(qkv, att);

    // 5. out-proj + residual -> LN1
    gemm_tc<<<dim3(66, 4), 256>>>(att, attn_out_w, attn_out_b, x0, y, ROWS, DM, DM, 0);
    ln_kernel<<<(ROWS + 7) / 8, 256>>>(y, ln1_g, ln1_b, x1, ROWS);

    // 6. FFN: relu(x@lin1^T) @ lin2^T + residual -> LN2
    gemm_tc<<<dim3(66, 4), 256>>>(x1, lin1_w, lin1_b, nullptr, f, ROWS, DM, DM, 1);
    gemm_tc<<<dim3(66, 4), 256>>>(f, lin2_w, lin2_b, x1, y, ROWS, DM, DM, 0);
    ln_kernel<<<(ROWS + 7) / 8, 256>>>(y, ln2_g, ln2_b, x2, ROWS);

    // 7. classifier head
    head_kernel<<<BB, 256>>>(x2, fc_w, fc_b, out);
}